// round 4
// baseline (speedup 1.0000x reference)
#include <cuda_runtime.h>
#include <cuda_bf16.h>

#define KDIM 256
#define TEMPF 1.0e8f
#define RPB 256          // rows per block (1 thread per row)
#define MAXC 8           // max window candidates per row

// Correctly-rounded (to ~2^-39 before final rounding) float exp for r in [-80, 0].
__device__ __forceinline__ float exp_cr(float r, const double* __restrict__ T)
{
    float nf = rintf(r * 46.166241f);                 // r * 32/ln2
    int n2 = (int)nf;
    int m  = n2 >> 5;
    int j  = n2 & 31;
    double fd = fma((double)nf, -2.1660849392498290e-2, (double)r);  // r - nf*ln2/32
    double p  = fma(fd, 1.0 / 24.0, 1.0 / 6.0);
    p = fma(fd, p, 0.5);
    p = fma(fd, p, 1.0);
    p = fma(fd, p, 1.0);
    float sf = (float)(T[j] * p);
    return sf * __int_as_float((m + 127) << 23);
}

__global__ __launch_bounds__(256, 4) void quantizer_kernel(
    const float* __restrict__ x,      // (rows)
    const float* __restrict__ cb,     // (256)
    float* __restrict__ soft,         // (rows, 256)
    float* __restrict__ hard,         // (rows, 256)
    float* __restrict__ quant,        // (rows)
    int rows)
{
    __shared__ float4 scb4[64];                 // codebook, natural order
    __shared__ double Texp[32];                 // 2^(j/32)

    const int tid  = threadIdx.x;
    const int row0 = blockIdx.x * RPB;
    const int row  = row0 + tid;

    if (tid < 64) scb4[tid] = reinterpret_cast<const float4*>(cb)[tid];
    if (tid < 32) Texp[tid] = exp2((double)tid * 0.03125);

    // ---- Phase 0: stream zeros over this block's output slabs FIRST so the
    // DRAM write stream drains while we compute. Full-sector STG.128 -> no RFO.
    {
        const float4 z = make_float4(0.f, 0.f, 0.f, 0.f);
        float4* ps = reinterpret_cast<float4*>(soft + (size_t)row0 * KDIM);
        float4* ph = reinterpret_cast<float4*>(hard + (size_t)row0 * KDIM);
        // RPB*KDIM floats = 16384 float4 per slab; 64 per thread
#pragma unroll 8
        for (int i = 0; i < 64; i++) {
            ps[tid + 256 * i] = z;
            ph[tid + 256 * i] = z;
        }
    }
    __syncthreads();   // codebook/Texp ready (also separates smem init)

    // ---------------- Phase 1: thread-per-row sparse compute (registers only) ----
    int   nc = 0, bk = 0;
    short idxs[MAXC];
    float pvals[MAXC];
    float qv = 0.0f;

    if (row < rows) {
        const float xv = x[row];

        // pass 1: amin over 256 entries (4 independent min chains)
        float m0 = 3.0e38f, m1 = 3.0e38f, m2 = 3.0e38f, m3 = 3.0e38f;
#pragma unroll 16
        for (int i = 0; i < 64; i++) {
            float4 c = scb4[i];
            m0 = fminf(m0, fabsf(xv - c.x));
            m1 = fminf(m1, fabsf(xv - c.y));
            m2 = fminf(m2, fabsf(xv - c.z));
            m3 = fminf(m3, fabsf(xv - c.w));
        }
        const float amin = fminf(fminf(m0, m1), fminf(m2, m3));

        // window: only entries with t = 1e8*(d - dmax) >= -104 can be nonzero
        const float d_est = __expf(-amin);
        const float wthr  = amin + 1.3e-6f / d_est;

        // pass 2: capture candidates (typically 1-2)
        float avs[MAXC], cvs[MAXC];
#pragma unroll 8
        for (int i = 0; i < 64; i++) {
            float4 c = scb4[i];
            float a0 = fabsf(xv - c.x);
            float a1 = fabsf(xv - c.y);
            float a2 = fabsf(xv - c.z);
            float a3 = fabsf(xv - c.w);
            if (a0 <= wthr && nc < MAXC) { idxs[nc] = (short)(4*i+0); avs[nc] = a0; cvs[nc] = c.x; nc++; }
            if (a1 <= wthr && nc < MAXC) { idxs[nc] = (short)(4*i+1); avs[nc] = a1; cvs[nc] = c.y; nc++; }
            if (a2 <= wthr && nc < MAXC) { idxs[nc] = (short)(4*i+2); avs[nc] = a2; cvs[nc] = c.z; nc++; }
            if (a3 <= wthr && nc < MAXC) { idxs[nc] = (short)(4*i+3); avs[nc] = a3; cvs[nc] = c.w; nc++; }
        }

        // accurate d on candidates; argmax with lowest-index tie-break
        float dcand[MAXC];
        float bd = -1.0f;
        for (int i = 0; i < nc; i++) {
            float di = exp_cr(-avs[i], Texp);
            dcand[i] = di;
            if (di > bd) { bd = di; bk = idxs[i]; }   // ascending k -> first-index ties
        }

        // softmax(TEMP*d), scale-then-subtract exactly like jax.nn.softmax.
        // Non-candidates: t = -amax <= -2.5e5 -> exp == 0 exactly (matches zero-fill).
        const float amax = __fmul_rn(TEMPF, bd);
        float sum = 0.0f, qp = 0.0f;
        for (int i = 0; i < nc; i++) {
            float t = __fadd_rn(__fmul_rn(TEMPF, dcand[i]), -amax);
            float s = __expf(t);
            pvals[i] = s;
            sum += s;
            qp  = __fmaf_rn(s, cvs[i], qp);
        }
        const float inv = 1.0f / sum;
        for (int i = 0; i < nc; i++) pvals[i] *= inv;
        qv = qp * inv;
    }

    // Order: all zero-fill stores (from every thread in the block) happen-before
    // the scatter patches below.
    __syncthreads();

    // ---------------- Phase 2: scatter-patch nonzeros (L2 dirty-merge) ----------
    if (row < rows) {
        float* srow = soft + (size_t)row * KDIM;
        for (int i = 0; i < nc; i++)
            srow[idxs[i]] = pvals[i];
        hard[(size_t)row * KDIM + bk] = 1.0f;
        quant[row] = qv;                      // coalesced across threads
    }
}

extern "C" void kernel_launch(void* const* d_in, const int* in_sizes, int n_in,
                              void* d_out, int out_size)
{
    const float* x  = (const float*)d_in[0];   // inputs (1024,512) f32
    const float* cb = (const float*)d_in[1];   // codebook (1,256) f32
    const int rows  = in_sizes[0];             // 524288

    float* out   = (float*)d_out;              // [soft | hard | quantized]
    float* soft  = out;
    float* hard  = out + (size_t)rows * KDIM;
    float* quant = out + 2ull * (size_t)rows * KDIM;

    const int blocks = (rows + RPB - 1) / RPB;
    quantizer_kernel<<<blocks, 256>>>(x, cb, soft, hard, quant, rows);
}

// round 5
// speedup vs baseline: 1.3437x; 1.3437x over previous
#include <cuda_runtime.h>
#include <cuda_bf16.h>

#define KDIM 256
#define TEMPF 1.0e8f
#define RPB 256          // rows per block (1 thread per row in phase 1)
#define MAXC 8           // max window candidates per row

// Device-global tables built by the prep kernel (once per replay, in-graph).
__device__ float  g_sorted[KDIM];   // codebook values ascending
__device__ short  g_perm[KDIM];     // g_perm[pos] = original k
__device__ double g_texp[32];       // 2^(j/32)

// Correctly-rounded (to ~2^-39 before final rounding) float exp for r in [-80, 0].
__device__ __forceinline__ float exp_cr(float r, const double* __restrict__ T)
{
    float nf = rintf(r * 46.166241f);                 // r * 32/ln2
    int n2 = (int)nf;
    int m  = n2 >> 5;
    int j  = n2 & 31;
    double fd = fma((double)nf, -2.1660849392498290e-2, (double)r);  // r - nf*ln2/32
    double p  = fma(fd, 1.0 / 24.0, 1.0 / 6.0);
    p = fma(fd, p, 0.5);
    p = fma(fd, p, 1.0);
    p = fma(fd, p, 1.0);
    float sf = (float)(T[j] * p);
    return sf * __int_as_float((m + 127) << 23);
}

// Rank-sort the 256-entry codebook (stable; values are distinct uniforms anyway).
__global__ void prep_kernel(const float* __restrict__ cb)
{
    __shared__ float v[KDIM];
    const int t = threadIdx.x;
    float my = cb[t];
    v[t] = my;
    __syncthreads();
    int rank = 0;
#pragma unroll 8
    for (int j = 0; j < KDIM; j++) {
        float vj = v[j];
        rank += (vj < my) || (vj == my && j < t);
    }
    g_sorted[rank] = my;
    g_perm[rank]   = (short)t;
    if (t < 32) g_texp[t] = exp2((double)t * 0.03125);
}

__global__ __launch_bounds__(256, 4) void quantizer_kernel(
    const float* __restrict__ x,      // (rows)
    float* __restrict__ soft,         // (rows, 256)
    float* __restrict__ hard,         // (rows, 256)
    float* __restrict__ quant,        // (rows)
    int rows)
{
    __shared__ float  ssc[KDIM];                // sorted codebook values
    __shared__ short  sperm[KDIM];              // sorted pos -> original k
    __shared__ double Texp[32];
    __shared__ int    s_bk[RPB];
    __shared__ int    s_n [RPB];
    __shared__ short  s_idx[RPB][MAXC];
    __shared__ float  s_val[RPB][MAXC];

    const int tid = threadIdx.x;
    ssc[tid]   = g_sorted[tid];
    sperm[tid] = g_perm[tid];
    if (tid < 32) Texp[tid] = g_texp[tid];
    __syncthreads();

    const int row0 = blockIdx.x * RPB;
    const int row  = row0 + tid;

    // ---------------- Phase 1: thread-per-row sparse compute ----------------
    if (row < rows) {
        const float xv = x[row];

        // branchless lower_bound: lo = #elements < xv, in [0,256]
        int lo = 0;
#pragma unroll
        for (int s = 128; s; s >>= 1) {
            int m = lo + s;
            if (m <= KDIM && ssc[m - 1] < xv) lo = m;
        }

        // nearest distance from the two neighbors
        const float aL = (lo > 0)    ? (xv - ssc[lo - 1]) : 3.0e38f;
        const float aR = (lo < KDIM) ? (ssc[lo] - xv)     : 3.0e38f;
        const float amin = fminf(aL, aR);

        // window: t = 1e8*(d - dmax) >= ~-35  <=>  a <= amin + ~3e-7/dmax.
        // Dropped entries have soft value <= e^-30 ~ 9e-14 -> negligible vs 1e-3.
        const float d_est = __expf(-amin);
        const float wthr  = amin + 3.0e-7f / d_est;

        // expand left/right over the contiguous sorted window
        int   nc = 0;
        float avs[MAXC], cvs[MAXC];
        short kks[MAXC];
        for (int p = lo - 1; p >= 0 && nc < MAXC; p--) {
            float a = xv - ssc[p];
            if (a > wthr) break;
            avs[nc] = a; cvs[nc] = ssc[p]; kks[nc] = sperm[p]; nc++;
        }
        for (int p = lo; p < KDIM && nc < MAXC; p++) {
            float a = ssc[p] - xv;
            if (a > wthr) break;
            avs[nc] = a; cvs[nc] = ssc[p]; kks[nc] = sperm[p]; nc++;
        }

        // accurate d on candidates; argmax with lowest-ORIGINAL-k tie-break
        float dcand[MAXC];
        float bd = -1.0f; int bk = 0;
        for (int i = 0; i < nc; i++) {
            float di = exp_cr(-avs[i], Texp);
            dcand[i] = di;
            int ki = kks[i];
            if (di > bd || (di == bd && ki < bk)) { bd = di; bk = ki; }
        }

        // softmax(TEMP*d): scale-then-subtract exactly like jax.nn.softmax.
        const float amax = __fmul_rn(TEMPF, bd);
        float sum = 0.0f, qp = 0.0f;
        float sv[MAXC];
        for (int i = 0; i < nc; i++) {
            float t = __fadd_rn(__fmul_rn(TEMPF, dcand[i]), -amax);
            float s = __expf(t);
            sv[i] = s;
            sum += s;
            qp  = __fmaf_rn(s, cvs[i], qp);
        }
        const float inv = 1.0f / sum;
        quant[row] = qp * inv;

        s_bk[tid] = bk;
        s_n [tid] = nc;
        for (int i = 0; i < nc; i++) {
            s_idx[tid][i] = kks[i];
            s_val[tid][i] = sv[i] * inv;
        }
    } else {
        s_n[tid] = 0; s_bk[tid] = -1;
    }
    __syncthreads();

    // ---------------- Phase 2: warp-per-row dense streaming stores ----------------
    const int lane = tid & 31;
    const int warp = tid >> 5;
    const int k0 = 4 * lane;          // entries k0..k0+3
    const int k1 = 128 + 4 * lane;    // entries k1..k1+3

    for (int rr = warp; rr < RPB; rr += 8) {
        const int grow = row0 + rr;
        if (grow >= rows) break;
        const int n  = s_n[rr];
        const int bk = s_bk[rr];
        const size_t base = (size_t)grow * KDIM;

        float4 sv0 = make_float4(0.f, 0.f, 0.f, 0.f);
        float4 sv1 = make_float4(0.f, 0.f, 0.f, 0.f);
        for (int i = 0; i < n; i++) {
            const int   ki = s_idx[rr][i];     // LDS broadcast
            const float vi = s_val[rr][i];
            sv0.x = (ki == k0    ) ? vi : sv0.x;
            sv0.y = (ki == k0 + 1) ? vi : sv0.y;
            sv0.z = (ki == k0 + 2) ? vi : sv0.z;
            sv0.w = (ki == k0 + 3) ? vi : sv0.w;
            sv1.x = (ki == k1    ) ? vi : sv1.x;
            sv1.y = (ki == k1 + 1) ? vi : sv1.y;
            sv1.z = (ki == k1 + 2) ? vi : sv1.z;
            sv1.w = (ki == k1 + 3) ? vi : sv1.w;
        }
        float4 hv0 = make_float4(bk == k0     ? 1.f : 0.f,
                                 bk == k0 + 1 ? 1.f : 0.f,
                                 bk == k0 + 2 ? 1.f : 0.f,
                                 bk == k0 + 3 ? 1.f : 0.f);
        float4 hv1 = make_float4(bk == k1     ? 1.f : 0.f,
                                 bk == k1 + 1 ? 1.f : 0.f,
                                 bk == k1 + 2 ? 1.f : 0.f,
                                 bk == k1 + 3 ? 1.f : 0.f);

        reinterpret_cast<float4*>(soft + base)[lane]       = sv0;
        reinterpret_cast<float4*>(soft + base + 128)[lane] = sv1;
        reinterpret_cast<float4*>(hard + base)[lane]       = hv0;
        reinterpret_cast<float4*>(hard + base + 128)[lane] = hv1;
    }
}

extern "C" void kernel_launch(void* const* d_in, const int* in_sizes, int n_in,
                              void* d_out, int out_size)
{
    const float* x  = (const float*)d_in[0];   // inputs (1024,512) f32
    const float* cb = (const float*)d_in[1];   // codebook (1,256) f32
    const int rows  = in_sizes[0];             // 524288

    float* out   = (float*)d_out;              // [soft | hard | quantized]
    float* soft  = out;
    float* hard  = out + (size_t)rows * KDIM;
    float* quant = out + 2ull * (size_t)rows * KDIM;

    prep_kernel<<<1, KDIM>>>(cb);
    const int blocks = (rows + RPB - 1) / RPB;
    quantizer_kernel<<<blocks, 256>>>(x, soft, hard, quant, rows);
}